// round 1
// baseline (speedup 1.0000x reference)
#include <cuda_runtime.h>
#include <math.h>

// ---------------- grid constants (1024 x 1024 raster) ----------------
#define NRC   1024
#define CSH   10
#define CMASK (NRC - 1)
#define NN    (NRC * NRC)
#define HL    (NRC * (NRC - 1))   // number of horizontal links

#define CG_ITERS 64
#define TOL2     1e-6             // CG_TOL^2

// ---------------- scratch (device globals; no allocation) ----------------
__device__ float d_g[NN];      // hydraulic gradient at nodes
__device__ float d_S[NN];      // stage conduit size
__device__ float d_x[NN];      // CG solution (potential)
__device__ float d_r[NN];      // CG residual
__device__ float d_p[NN];      // CG direction
__device__ float d_Ap[NN];     // A*p
__device__ float d_gap[NN];    // gap_base per node
__device__ float d_k[NN];      // current stage roc
__device__ float d_ksum[NN];   // accumulated k1 + 2k2 + 2k3 (+k4)
__device__ double d_rs[72];    // ||r_k||^2 per iteration (rs[0] = ||b||^2)
__device__ double d_pAp[72];   // p.Ap per iteration

// ---------------- block reduction -> atomicAdd ----------------
__device__ __forceinline__ void reduceAdd(double v, double* dst) {
#pragma unroll
    for (int o = 16; o > 0; o >>= 1) v += __shfl_down_sync(0xffffffffu, v, o);
    __shared__ double s[8];
    int lane = threadIdx.x & 31, w = threadIdx.x >> 5;
    if (lane == 0) s[w] = v;
    __syncthreads();
    if (threadIdx.x < 8) {
        v = s[threadIdx.x];
#pragma unroll
        for (int o = 4; o > 0; o >>= 1) v += __shfl_down_sync(0xffu, v, o);
        if (threadIdx.x == 0) atomicAdd(dst, v);
    }
}

// ---------------- one-time: gap_base from sliding_velocity ----------------
__global__ void k_gap(const float* __restrict__ sv) {
    int i = blockIdx.x * blockDim.x + threadIdx.x;
    int c = i & CMASK, r = i >> CSH;
    float s = 0.f, n = 0.f;
    if (c < NRC - 1) { s += sv[r * (NRC - 1) + c];     n += 1.f; }  // east h-link
    if (c > 0)       { s += sv[r * (NRC - 1) + c - 1]; n += 1.f; }  // west h-link
    if (r < NRC - 1) { s += sv[HL + i];                n += 1.f; }  // south v-link
    if (r > 0)       { s += sv[HL + i - NRC];          n += 1.f; }  // north v-link
    float slide = (s / 31556926.0f) / fmaxf(n, 1.0f);
    d_gap[i] = fabsf(slide) * 0.03f;
}

// ---------------- stage init: S, g, zero CG scalars ----------------
__global__ void k_stageA(const float* __restrict__ conduit,
                         const float* __restrict__ discharge, float coef) {
    int i = blockIdx.x * blockDim.x + threadIdx.x;
    if (i < 72) { d_rs[i] = 0.0; d_pAp[i] = 0.0; }
    float S = conduit[i] + coef * d_k[i];
    // S^1.25 = S * S^0.25
    float g = discharge[i] * 0.0405f * (S * sqrtf(sqrtf(S)));
    g = g * g;
    d_S[i] = S;
    d_g[i] = g;
}

// ---------------- build b = flux_div(g_link); set r=p=b, x=0; accumulate ||b||^2 ----------------
__global__ void k_stageB(const int* __restrict__ status,
                         const float* __restrict__ geo,
                         const float* __restrict__ fw,
                         const float* __restrict__ area) {
    int i = blockIdx.x * blockDim.x + threadIdx.x;
    int c = i & CMASK, r = i >> CSH;
    float coef = fw[0] / area[0];
    int   sti = status[i];
    float gi = d_g[i], geoi = geo[i];
    float acc = 0.f;
    if (c < NRC - 1) {   // east link, i is tail: +
        int j = i + 1;
        bool ina = (sti != 0) | (status[j] != 0);
        acc += ina ? 0.5f * (geoi + geo[j]) : 0.5f * (gi + d_g[j]);
    }
    if (c > 0) {         // west link, i is head: -
        int j = i - 1;
        bool ina = (sti != 0) | (status[j] != 0);
        acc -= ina ? 0.5f * (geoi + geo[j]) : 0.5f * (gi + d_g[j]);
    }
    if (r < NRC - 1) {   // south link, i is tail: +
        int j = i + NRC;
        bool ina = (sti != 0) | (status[j] != 0);
        acc += ina ? 0.5f * (geoi + geo[j]) : 0.5f * (gi + d_g[j]);
    }
    if (r > 0) {         // north link, i is head: -
        int j = i - NRC;
        bool ina = (sti != 0) | (status[j] != 0);
        acc -= ina ? 0.5f * (geoi + geo[j]) : 0.5f * (gi + d_g[j]);
    }
    float b = coef * acc;
    d_r[i] = b;
    d_p[i] = b;
    d_x[i] = 0.f;
    reduceAdd((double)b * (double)b, &d_rs[0]);
}

// ---------------- CG iteration k: Ap = laplace(p), accumulate p.Ap ----------------
__global__ void k_cg1(int k, const float* __restrict__ ll,
                      const float* __restrict__ fw, const float* __restrict__ area) {
    double rs = d_rs[k];
    if (!(rs > TOL2 * d_rs[0])) return;   // emulate while-loop gate
    int i = blockIdx.x * blockDim.x + threadIdx.x;
    int c = i & CMASK, r = i >> CSH;
    float coefA = fw[0] / (ll[0] * area[0]);
    float pc = d_p[i];
    float sum = 0.f; int deg = 0;
    if (c > 0)       { sum += d_p[i - 1];   deg++; }
    if (c < NRC - 1) { sum += d_p[i + 1];   deg++; }
    if (r > 0)       { sum += d_p[i - NRC]; deg++; }
    if (r < NRC - 1) { sum += d_p[i + NRC]; deg++; }
    float Ap = coefA * (sum - (float)deg * pc);
    d_Ap[i] = Ap;
    reduceAdd((double)pc * (double)Ap, &d_pAp[k]);
}

// ---------------- CG iteration k: alpha; x += a p; r -= a Ap; accumulate ||r||^2 ----------------
__global__ void k_cg2(int k) {
    double rs = d_rs[k];
    if (!(rs > TOL2 * d_rs[0])) return;
    float alpha = (float)(rs / d_pAp[k]);
    int i = blockIdx.x * blockDim.x + threadIdx.x;
    d_x[i] += alpha * d_p[i];
    float rn = d_r[i] - alpha * d_Ap[i];
    d_r[i] = rn;
    reduceAdd((double)rn * (double)rn, &d_rs[k + 1]);
}

// ---------------- CG iteration k: beta; p = r + beta p ----------------
__global__ void k_cg3(int k) {
    double rs = d_rs[k];
    if (!(rs > TOL2 * d_rs[0])) return;
    float beta = (float)(d_rs[k + 1] / rs);
    int i = blockIdx.x * blockDim.x + threadIdx.x;
    d_p[i] = d_r[i] + beta * d_p[i];
}

// ---------------- stage finalize: roc, accumulate RK sum, final output ----------------
__global__ void k_stageC(const float* __restrict__ conduit,
                         const float* __restrict__ discharge,
                         const float* __restrict__ geo,
                         int stage, float* __restrict__ out) {
    int i = blockIdx.x * blockDim.x + threadIdx.x;
    float S = d_S[i], g = d_g[i];
    float pres = geo[i] - d_x[i];
    float melt = 1.3455e-9f * discharge[i] * g;
    float gap  = d_gap[i] * (1.0f - tanhf(S * (1.0f / 5.74f)));
    float clo  = 7.11e-24f * pres * pres * pres * S;
    float kk = melt + gap - clo;
    d_k[i] = kk;
    if (stage == 0)      d_ksum[i] = kk;
    else if (stage == 3) out[i] = conduit[i] + (3600.0f / 6.0f) * (d_ksum[i] + kk);
    else                 d_ksum[i] += 2.0f * kk;
}

extern "C" void kernel_launch(void* const* d_in, const int* in_sizes, int n_in,
                              void* d_out, int out_size) {
    const float* conduit   = (const float*)d_in[0];
    const float* discharge = (const float*)d_in[1];
    const float* geo       = (const float*)d_in[2];
    const float* sv        = (const float*)d_in[3];
    const float* ll        = (const float*)d_in[4];
    const float* fw        = (const float*)d_in[5];
    const float* area      = (const float*)d_in[6];
    const int*   status    = (const int*)  d_in[9];
    float* out = (float*)d_out;

    dim3 blk(256), grd(NN / 256);
    const float coefs[4] = {0.f, 1800.f, 1800.f, 3600.f};

    k_gap<<<grd, blk>>>(sv);
    for (int s = 0; s < 4; s++) {
        k_stageA<<<grd, blk>>>(conduit, discharge, coefs[s]);
        k_stageB<<<grd, blk>>>(status, geo, fw, area);
        for (int k = 0; k < CG_ITERS; k++) {
            k_cg1<<<grd, blk>>>(k, ll, fw, area);
            k_cg2<<<grd, blk>>>(k);
            k_cg3<<<grd, blk>>>(k);
        }
        k_stageC<<<grd, blk>>>(conduit, discharge, geo, s, out);
    }
}

// round 2
// speedup vs baseline: 2.6812x; 2.6812x over previous
#include <cuda_runtime.h>
#include <math.h>

#define NRC 1024
#define NN  (NRC * NRC)
#define HL  (NRC * (NRC - 1))
#define NB  128          // blocks (all co-resident: 128 <= 148 SMs)
#define TPB 1024
#define RPB 8            // rows per block

// ---------------- device scratch (no allocation) ----------------
__device__ float  d_gh[NN];       // g halo (boundary rows)
__device__ float  d_ph[NN];       // p halo (boundary rows)
__device__ double d_partA[NB];    // per-block partial: p.Ap
__device__ double d_partB[NB];    // per-block partial: r.r
__device__ unsigned d_cnt = 0;    // barrier arrival count (self-resetting)
__device__ unsigned d_gen = 0;    // barrier generation (monotonic, replay-safe)

// ---------------- software grid barrier (all NB blocks resident) ----------------
__device__ __forceinline__ void grid_bar() {
    __threadfence();
    __syncthreads();
    if (threadIdx.x == 0) {
        unsigned g = atomicAdd(&d_gen, 0u);
        if (atomicAdd(&d_cnt, 1u) == NB - 1u) {
            atomicExch(&d_cnt, 0u);
            __threadfence();
            atomicAdd(&d_gen, 1u);
        } else {
            while (atomicAdd(&d_gen, 0u) == g) { __nanosleep(64); }
            __threadfence();
        }
    }
    __syncthreads();
}

__device__ __forceinline__ double warp_red(double v) {
#pragma unroll
    for (int o = 16; o > 0; o >>= 1) v += __shfl_down_sync(0xffffffffu, v, o);
    return v;
}

// block-sum of v -> store to dst (one slot per block), deterministic tree
__device__ __forceinline__ void block_red_store(double v, double* dst) {
    __shared__ double sw[32];
    v = warp_red(v);
    int lane = threadIdx.x & 31, w = threadIdx.x >> 5;
    if (lane == 0) sw[w] = v;
    __syncthreads();
    if (w == 0) {
        v = warp_red(sw[lane]);
        if (lane == 0) __stcg(dst, v);
    }
}

// after grid_bar: sum the NB per-block partials, broadcast to whole block
__device__ __forceinline__ double red_finish(const double* part) {
    __shared__ double s4[4];
    __shared__ double bc;
    int t = threadIdx.x;
    if (t < NB) {
        double v = __ldcg(part + t);
        v = warp_red(v);
        if ((t & 31) == 0) s4[t >> 5] = v;
    }
    __syncthreads();
    if (t == 0) bc = s4[0] + s4[1] + s4[2] + s4[3];
    __syncthreads();
    return bc;
}

__global__ void __launch_bounds__(TPB, 1)
conduit_persist(const float* __restrict__ conduit, const float* __restrict__ discharge,
                const float* __restrict__ geo,     const float* __restrict__ sv,
                const float* __restrict__ ll,      const float* __restrict__ fw,
                const float* __restrict__ area,    const int* __restrict__ status,
                float* __restrict__ out)
{
    __shared__ float sp[RPB][NRC];   // block's 8 rows of g, then p (reused)

    const int t  = threadIdx.x;      // column
    const int b  = blockIdx.x;
    const int r0 = b * RPB;

    const float fw0 = __ldg(fw), ll0 = __ldg(ll), ar0 = __ldg(area);
    const float coefb = fw0 / ar0;            // flux_div face coeff
    const float coefA = fw0 / (ll0 * ar0);    // laplace coeff

    // ---- gap_base (one-time, registers) ----
    float gap[RPB];
#pragma unroll
    for (int j = 0; j < RPB; j++) {
        int row = r0 + j, i = row * NRC + t;
        float s = 0.f, n = 0.f;
        if (t   < NRC - 1) { s += __ldg(&sv[row * (NRC - 1) + t]);     n += 1.f; }
        if (t   > 0)       { s += __ldg(&sv[row * (NRC - 1) + t - 1]); n += 1.f; }
        if (row < NRC - 1) { s += __ldg(&sv[HL + i]);                  n += 1.f; }
        if (row > 0)       { s += __ldg(&sv[HL + i - NRC]);            n += 1.f; }
        float sl = (s * (1.0f / 31556926.0f)) / fmaxf(n, 1.0f);
        gap[j] = fabsf(sl) * 0.03f;
    }

    float kk[RPB], ksum[RPB], x[RPB], rr[RPB], Ap[RPB];
#pragma unroll
    for (int j = 0; j < RPB; j++) { kk[j] = 0.f; ksum[j] = 0.f; }

    const float coefs[4] = {0.f, 1800.f, 1800.f, 3600.f};

    for (int s = 0; s < 4; s++) {
        const float cst = coefs[s];

        // ---- phase 1: S, g -> shared (+ halo rows) ----
#pragma unroll
        for (int j = 0; j < RPB; j++) {
            int row = r0 + j, i = row * NRC + t;
            float S = __ldg(&conduit[i]) + cst * kk[j];
            float g = __ldg(&discharge[i]) * 0.0405f * (S * sqrtf(sqrtf(S)));
            g = g * g;
            sp[j][t] = g;
            if (j == 0 || j == RPB - 1) __stcg(&d_gh[i], g);
        }
        grid_bar();

        // ---- phase 2: b = flux_div(g_link); r = p = b; x = 0; ||b||^2 ----
        double dacc = 0.0;
#pragma unroll
        for (int j = 0; j < RPB; j++) {
            int row = r0 + j, i = row * NRC + t;
            int   sti  = __ldg(&status[i]);
            float gi   = sp[j][t];
            float geoi = __ldg(&geo[i]);
            float acc  = 0.f;
            if (t < NRC - 1) {             // east link (i tail): +
                int jn = i + 1;
                acc += ((sti | __ldg(&status[jn])) != 0)
                     ? 0.5f * (geoi + __ldg(&geo[jn]))
                     : 0.5f * (gi + sp[j][t + 1]);
            }
            if (t > 0) {                   // west link (i head): -
                int jn = i - 1;
                acc -= ((sti | __ldg(&status[jn])) != 0)
                     ? 0.5f * (geoi + __ldg(&geo[jn]))
                     : 0.5f * (gi + sp[j][t - 1]);
            }
            if (row < NRC - 1) {           // south link (i tail): +
                int jn = i + NRC;
                float gn = (j < RPB - 1) ? sp[j + 1][t] : __ldcg(&d_gh[jn]);
                acc += ((sti | __ldg(&status[jn])) != 0)
                     ? 0.5f * (geoi + __ldg(&geo[jn]))
                     : 0.5f * (gi + gn);
            }
            if (row > 0) {                 // north link (i head): -
                int jn = i - NRC;
                float gn = (j > 0) ? sp[j - 1][t] : __ldcg(&d_gh[jn]);
                acc -= ((sti | __ldg(&status[jn])) != 0)
                     ? 0.5f * (geoi + __ldg(&geo[jn]))
                     : 0.5f * (gi + gn);
            }
            float bv = coefb * acc;
            x[j] = 0.f; rr[j] = bv;
            dacc += (double)bv * (double)bv;
        }
        __syncthreads();                   // all g reads done before overwriting sp with p
#pragma unroll
        for (int j = 0; j < RPB; j++) {
            int i = (r0 + j) * NRC + t;
            sp[j][t] = rr[j];
            if (j == 0 || j == RPB - 1) __stcg(&d_ph[i], rr[j]);
        }
        block_red_store(dacc, &d_partB[b]);
        grid_bar();
        double bnorm2 = red_finish(d_partB);
        double rs     = bnorm2;
        double atol2  = 1e-6 * bnorm2;     // CG_TOL^2 * ||b||^2

        // ---- CG loop (uniform early break across all blocks) ----
        for (int it = 0; it < 64; ++it) {
            if (!(rs > atol2)) break;
            // SpMV: Ap = laplace(p); p.Ap
            double pap = 0.0;
#pragma unroll
            for (int j = 0; j < RPB; j++) {
                int row = r0 + j, i = row * NRC + t;
                float pc = sp[j][t];
                float sum = 0.f, deg = 0.f;
                if (t > 0)         { sum += sp[j][t - 1]; deg += 1.f; }
                if (t < NRC - 1)   { sum += sp[j][t + 1]; deg += 1.f; }
                if (row > 0)       { sum += (j > 0)       ? sp[j - 1][t] : __ldcg(&d_ph[i - NRC]); deg += 1.f; }
                if (row < NRC - 1) { sum += (j < RPB - 1) ? sp[j + 1][t] : __ldcg(&d_ph[i + NRC]); deg += 1.f; }
                float ap = coefA * (sum - deg * pc);
                Ap[j] = ap;
                pap += (double)pc * (double)ap;
            }
            block_red_store(pap, &d_partA[b]);
            grid_bar();
            double paps = red_finish(d_partA);
            float alpha = (float)(rs / paps);

            double rsn = 0.0;
#pragma unroll
            for (int j = 0; j < RPB; j++) {
                x[j] += alpha * sp[j][t];
                float rn = rr[j] - alpha * Ap[j];
                rr[j] = rn;
                rsn += (double)rn * (double)rn;
            }
            block_red_store(rsn, &d_partB[b]);
            grid_bar();
            double rs_new = red_finish(d_partB);
            float beta = (float)(rs_new / rs);

#pragma unroll
            for (int j = 0; j < RPB; j++) {
                int i = (r0 + j) * NRC + t;
                float pn = rr[j] + beta * sp[j][t];
                sp[j][t] = pn;
                if (j == 0 || j == RPB - 1) __stcg(&d_ph[i], pn);
            }
            rs = rs_new;
            grid_bar();
        }

        // ---- stage end: roc, RK accumulation ----
#pragma unroll
        for (int j = 0; j < RPB; j++) {
            int i = (r0 + j) * NRC + t;
            float c = __ldg(&conduit[i]);
            float q = __ldg(&discharge[i]);
            float S = c + cst * kk[j];
            float g = q * 0.0405f * (S * sqrtf(sqrtf(S)));
            g = g * g;
            float pres = __ldg(&geo[i]) - x[j];
            float nk = 1.3455e-9f * q * g
                     + gap[j] * (1.0f - tanhf(S * (1.0f / 5.74f)))
                     - 7.11e-24f * pres * pres * pres * S;
            if (s == 0)      ksum[j] = nk;
            else if (s == 3) out[i]  = c + 600.0f * (ksum[j] + nk);
            else             ksum[j] += 2.0f * nk;
            kk[j] = nk;
        }
    }
}

extern "C" void kernel_launch(void* const* d_in, const int* in_sizes, int n_in,
                              void* d_out, int out_size) {
    const float* conduit   = (const float*)d_in[0];
    const float* discharge = (const float*)d_in[1];
    const float* geo       = (const float*)d_in[2];
    const float* sv        = (const float*)d_in[3];
    const float* ll        = (const float*)d_in[4];
    const float* fw        = (const float*)d_in[5];
    const float* area      = (const float*)d_in[6];
    const int*   status    = (const int*)  d_in[9];
    float* out = (float*)d_out;

    conduit_persist<<<NB, TPB>>>(conduit, discharge, geo, sv, ll, fw, area, status, out);
}

// round 4
// speedup vs baseline: 2.8624x; 1.0676x over previous
#include <cuda_runtime.h>
#include <math.h>

#define NRC 1024
#define NN  (NRC * NRC)
#define HL  (NRC * (NRC - 1))
#define NB  128          // blocks (all co-resident: 128 <= 148 SMs)
#define TPB 1024
#define RPB 8            // rows per block

// ---------------- device scratch (no allocation) ----------------
__device__ float  d_gh[NN];              // g halo (stage setup only)
__device__ float  d_ph[NN];              // initial p (=b) halo (stage setup only)
__device__ float  d_hr [2][NB * 2][NRC]; // published boundary r   (double-buffered)
__device__ float  d_hAp[2][NB * 2][NRC]; // published boundary Ap  (double-buffered)
__device__ double d_pA[2][NB];           // partials: p.Ap  (or ||b||^2 at setup)
__device__ double d_pB[2][NB];           // partials: r.Ap
__device__ double d_pC[2][NB];           // partials: Ap.Ap
__device__ unsigned d_cnt = 0;           // barrier arrival count (self-resetting)
__device__ unsigned d_gen = 0;           // barrier generation (monotonic, replay-safe)

// ---------------- PROVEN grid barrier (R2 verbatim: atomic poll + nanosleep) ----------------
__device__ __forceinline__ void grid_bar() {
    __threadfence();
    __syncthreads();
    if (threadIdx.x == 0) {
        unsigned g = atomicAdd(&d_gen, 0u);
        if (atomicAdd(&d_cnt, 1u) == NB - 1u) {
            atomicExch(&d_cnt, 0u);
            __threadfence();
            atomicAdd(&d_gen, 1u);
        } else {
            while (atomicAdd(&d_gen, 0u) == g) { __nanosleep(64); }
            __threadfence();
        }
    }
    __syncthreads();
}

__device__ __forceinline__ double warp_red(double v) {
#pragma unroll
    for (int o = 16; o > 0; o >>= 1) v += __shfl_down_sync(0xffffffffu, v, o);
    return v;
}

// store three block-sums into per-block slots of the chosen buffer
__device__ __forceinline__ void block_red_store3(double a, double bb, double c,
                                                 double* A, double* B, double* C, int b) {
    __shared__ double swA[32], swB[32], swC[32];
    a  = warp_red(a);
    bb = warp_red(bb);
    c  = warp_red(c);
    int lane = threadIdx.x & 31, w = threadIdx.x >> 5;
    if (lane == 0) { swA[w] = a; swB[w] = bb; swC[w] = c; }
    __syncthreads();
    if (w == 0) {
        double v = warp_red(swA[lane]);
        if (lane == 0) __stcg(&A[b], v);
    } else if (w == 1) {
        double v = warp_red(swB[lane]);
        if (lane == 0) __stcg(&B[b], v);
    } else if (w == 2) {
        double v = warp_red(swC[lane]);
        if (lane == 0) __stcg(&C[b], v);
    }
}

// after grid_bar: sum the NB per-block partials (3 components), broadcast
__device__ __forceinline__ void red_finish3(const double* A, const double* B, const double* C,
                                            double& oA, double& oB, double& oC) {
    __shared__ double s12[12];
    __shared__ double bc[3];
    int t = threadIdx.x;
    if (t < 3 * NB) {
        int comp = t >> 7;
        int idx  = t & (NB - 1);
        const double* src = (comp == 0) ? A : (comp == 1) ? B : C;
        double v = __ldcg(src + idx);
        v = warp_red(v);
        if ((t & 31) == 0) s12[t >> 5] = v;
    }
    __syncthreads();
    if (t < 3) bc[t] = s12[t * 4] + s12[t * 4 + 1] + s12[t * 4 + 2] + s12[t * 4 + 3];
    __syncthreads();
    oA = bc[0]; oB = bc[1]; oC = bc[2];
}

__global__ void __launch_bounds__(TPB, 1)
conduit_persist(const float* __restrict__ conduit, const float* __restrict__ discharge,
                const float* __restrict__ geo,     const float* __restrict__ sv,
                const float* __restrict__ ll,      const float* __restrict__ fw,
                const float* __restrict__ area,    const int* __restrict__ status,
                float* __restrict__ out)
{
    __shared__ float sp[RPB][NRC];   // block's 8 rows: g, then p (reused)

    const int t  = threadIdx.x;      // column
    const int b  = blockIdx.x;
    const int r0 = b * RPB;

    const float fw0 = __ldg(fw), ll0 = __ldg(ll), ar0 = __ldg(area);
    const float coefb = fw0 / ar0;            // flux_div face coeff
    const float coefA = fw0 / (ll0 * ar0);    // laplace coeff

    // ---- gap_base (one-time) ----
    float gap[RPB];
#pragma unroll
    for (int j = 0; j < RPB; j++) {
        int row = r0 + j, i = row * NRC + t;
        float s = 0.f, n = 0.f;
        if (t   < NRC - 1) { s += __ldg(&sv[row * (NRC - 1) + t]);     n += 1.f; }
        if (t   > 0)       { s += __ldg(&sv[row * (NRC - 1) + t - 1]); n += 1.f; }
        if (row < NRC - 1) { s += __ldg(&sv[HL + i]);                  n += 1.f; }
        if (row > 0)       { s += __ldg(&sv[HL + i - NRC]);            n += 1.f; }
        float sl = (s * (1.0f / 31556926.0f)) / fmaxf(n, 1.0f);
        gap[j] = fabsf(sl) * 0.03f;
    }

    float kk[RPB], ksum[RPB], x[RPB], rr[RPB], Ap[RPB];
    float gN = 0.f, gS = 0.f;        // ghost p rows (r0-1 and r0+RPB)
#pragma unroll
    for (int j = 0; j < RPB; j++) { kk[j] = 0.f; ksum[j] = 0.f; }

    const float coefs[4] = {0.f, 1800.f, 1800.f, 3600.f};
    const int slotN = b * 2;                 // my north boundary slot (row r0)
    const int slotS = b * 2 + 1;             // my south boundary slot (row r0+7)

    for (int s = 0; s < 4; s++) {
        const float cst = coefs[s];

        // ---- setup 1: S, g -> shared (+ halo rows to d_gh) ----
#pragma unroll
        for (int j = 0; j < RPB; j++) {
            int row = r0 + j, i = row * NRC + t;
            float S = __ldg(&conduit[i]) + cst * kk[j];
            float g = __ldg(&discharge[i]) * 0.0405f * (S * sqrtf(sqrtf(S)));
            g = g * g;
            sp[j][t] = g;
            if (j == 0 || j == RPB - 1) __stcg(&d_gh[i], g);
        }
        grid_bar();   // setup bar 1

        // ---- setup 2: b = flux_div(g_link); r = p = b; x = 0; ||b||^2 ----
        double dacc = 0.0;
#pragma unroll
        for (int j = 0; j < RPB; j++) {
            int row = r0 + j, i = row * NRC + t;
            int   sti  = __ldg(&status[i]);
            float gi   = sp[j][t];
            float geoi = __ldg(&geo[i]);
            float acc  = 0.f;
            if (t < NRC - 1) {
                int jn = i + 1;
                acc += ((sti | __ldg(&status[jn])) != 0)
                     ? 0.5f * (geoi + __ldg(&geo[jn]))
                     : 0.5f * (gi + sp[j][t + 1]);
            }
            if (t > 0) {
                int jn = i - 1;
                acc -= ((sti | __ldg(&status[jn])) != 0)
                     ? 0.5f * (geoi + __ldg(&geo[jn]))
                     : 0.5f * (gi + sp[j][t - 1]);
            }
            if (row < NRC - 1) {
                int jn = i + NRC;
                float gn = (j < RPB - 1) ? sp[j + 1][t] : __ldcg(&d_gh[jn]);
                acc += ((sti | __ldg(&status[jn])) != 0)
                     ? 0.5f * (geoi + __ldg(&geo[jn]))
                     : 0.5f * (gi + gn);
            }
            if (row > 0) {
                int jn = i - NRC;
                float gn = (j > 0) ? sp[j - 1][t] : __ldcg(&d_gh[jn]);
                acc -= ((sti | __ldg(&status[jn])) != 0)
                     ? 0.5f * (geoi + __ldg(&geo[jn]))
                     : 0.5f * (gi + gn);
            }
            float bv = coefb * acc;
            x[j] = 0.f; rr[j] = bv;
            dacc += (double)bv * (double)bv;
        }
        __syncthreads();                  // g reads done before overwriting sp with p
#pragma unroll
        for (int j = 0; j < RPB; j++) {
            int i = (r0 + j) * NRC + t;
            sp[j][t] = rr[j];
            if (j == 0 || j == RPB - 1) __stcg(&d_ph[i], rr[j]);
        }
        block_red_store3(dacc, 0.0, 0.0, d_pA[1], d_pB[1], d_pC[1], b);
        grid_bar();   // setup bar 2

        // ghost p init (= neighbor boundary b)
        gN = (b > 0)      ? __ldcg(&d_ph[(r0 - 1)   * NRC + t]) : 0.f;
        gS = (b < NB - 1) ? __ldcg(&d_ph[(r0 + RPB) * NRC + t]) : 0.f;

        double bnorm2, duB, duC;
        red_finish3(d_pA[1], d_pB[1], d_pC[1], bnorm2, duB, duC);
        double rs    = bnorm2;
        double atol2 = 1e-6 * bnorm2;     // CG_TOL^2 * ||b||^2

        // ---- CG loop: ONE barrier per iteration ----
        for (int it = 0; it < 64; ++it) {
            if (!(rs > atol2)) break;
            const int buf = it & 1;

            // SpMV (ghost rows from registers) + three dots
            double pap = 0.0, rap = 0.0, apap = 0.0;
#pragma unroll
            for (int j = 0; j < RPB; j++) {
                int row = r0 + j;
                float pc = sp[j][t];
                float sum = 0.f, deg = 0.f;
                if (t > 0)         { sum += sp[j][t - 1]; deg += 1.f; }
                if (t < NRC - 1)   { sum += sp[j][t + 1]; deg += 1.f; }
                if (row > 0)       { sum += (j > 0)       ? sp[j - 1][t] : gN; deg += 1.f; }
                if (row < NRC - 1) { sum += (j < RPB - 1) ? sp[j + 1][t] : gS; deg += 1.f; }
                float ap = coefA * (sum - deg * pc);
                Ap[j] = ap;
                pap  += (double)pc    * (double)ap;
                rap  += (double)rr[j] * (double)ap;
                apap += (double)ap    * (double)ap;
            }
            // publish boundary r_k and Ap_k (pre-update values) for neighbors
            __stcg(&d_hr [buf][slotN][t], rr[0]);
            __stcg(&d_hAp[buf][slotN][t], Ap[0]);
            __stcg(&d_hr [buf][slotS][t], rr[RPB - 1]);
            __stcg(&d_hAp[buf][slotS][t], Ap[RPB - 1]);

            block_red_store3(pap, rap, apap, d_pA[buf], d_pB[buf], d_pC[buf], b);
            grid_bar();   // the ONLY barrier this iteration

            double paps, raps, apaps;
            red_finish3(d_pA[buf], d_pB[buf], d_pC[buf], paps, raps, apaps);

            double alpha  = rs / paps;
            double rs_new = rs - 2.0 * alpha * raps + alpha * alpha * apaps;
            if (rs_new < 0.0) rs_new = 0.0;
            float  af = (float)alpha;
            float  bf = (float)(rs_new / rs);

            // fused update: x += a p ; r -= a Ap ; p = r + beta p
#pragma unroll
            for (int j = 0; j < RPB; j++) {
                float pc = sp[j][t];
                x[j] += af * pc;
                float rn = rr[j] - af * Ap[j];
                rr[j] = rn;
                sp[j][t] = rn + bf * pc;
            }
            // advance ghost p with IDENTICAL float-op order as neighbor's update
            if (b > 0) {
                float hr  = __ldcg(&d_hr [buf][slotN - 1][t]);   // neighbor's south bnd
                float hap = __ldcg(&d_hAp[buf][slotN - 1][t]);
                float rn  = hr - af * hap;
                gN = rn + bf * gN;
            }
            if (b < NB - 1) {
                float hr  = __ldcg(&d_hr [buf][slotS + 1][t]);   // neighbor's north bnd
                float hap = __ldcg(&d_hAp[buf][slotS + 1][t]);
                float rn  = hr - af * hap;
                gS = rn + bf * gS;
            }
            rs = rs_new;
        }

        // ---- stage end: roc, RK accumulation ----
#pragma unroll
        for (int j = 0; j < RPB; j++) {
            int i = (r0 + j) * NRC + t;
            float c = __ldg(&conduit[i]);
            float q = __ldg(&discharge[i]);
            float S = c + cst * kk[j];
            float g = q * 0.0405f * (S * sqrtf(sqrtf(S)));
            g = g * g;
            float pres = __ldg(&geo[i]) - x[j];
            float nk = 1.3455e-9f * q * g
                     + gap[j] * (1.0f - tanhf(S * (1.0f / 5.74f)))
                     - 7.11e-24f * pres * pres * pres * S;
            if (s == 0)      ksum[j] = nk;
            else if (s == 3) out[i]  = c + 600.0f * (ksum[j] + nk);
            else             ksum[j] += 2.0f * nk;
            kk[j] = nk;
        }
    }
}

extern "C" void kernel_launch(void* const* d_in, const int* in_sizes, int n_in,
                              void* d_out, int out_size) {
    const float* conduit   = (const float*)d_in[0];
    const float* discharge = (const float*)d_in[1];
    const float* geo       = (const float*)d_in[2];
    const float* sv        = (const float*)d_in[3];
    const float* ll        = (const float*)d_in[4];
    const float* fw        = (const float*)d_in[5];
    const float* area      = (const float*)d_in[6];
    const int*   status    = (const int*)  d_in[9];
    float* out = (float*)d_out;

    conduit_persist<<<NB, TPB>>>(conduit, discharge, geo, sv, ll, fw, area, status, out);
}